// round 1
// baseline (speedup 1.0000x reference)
#include <cuda_runtime.h>
#include <math.h>

#define NB 16
#define NA 5
#define NH 96
#define NW 96
#define NHW (NH * NW)          // 9216
#define TT 50

__constant__ float c_aw[NA] = {1.3221f, 3.19275f, 5.05587f, 9.47112f, 11.2364f};
__constant__ float c_ah[NA] = {1.73145f, 4.00944f, 8.09892f, 4.84053f, 10.0071f};

__device__ double g_acc;
__device__ float4 g_tA[NB * TT];   // xlo, xhi, ylo, yhi (gt box extents)
__device__ float4 g_tB[NB * TT];   // gw, gh, 0.6*gw*gh, unused
__device__ int    g_nv[NB];        // number of valid (prefix) targets per batch

__device__ __forceinline__ float sigmoidf_(float x) { return 1.f / (1.f + expf(-x)); }

// Predicate: does any valid gt box have IoU > 0.6 with the pred box?
// Division-free: iou > 0.6  <=>  1.6*carea > 0.6*(a_pred + a_gt), carea > 0.
__device__ __forceinline__ bool iou_over(const float4* __restrict__ A,
                                         const float4* __restrict__ B, int nv,
                                         float xlo, float xhi, float ylo, float yhi,
                                         float pw, float ph, float c1)
{
    for (int k = 0; k < nv; k++) {
        float4 a = A[k];
        float4 b = B[k];
        float uw = fmaxf(xhi, a.y) - fminf(xlo, a.x);
        float cw = pw + b.x - uw;
        float uh = fmaxf(yhi, a.w) - fminf(ylo, a.z);
        float ch = ph + b.y - uh;
        if (cw > 0.f && ch > 0.f && 1.6f * (cw * ch) > c1 + b.z) return true;
    }
    return false;
}

// ---------------------------------------------------------------------------
// Kernel 0: per-target prep + all sparse (scattered-cell) loss contributions.
// One block of NB*TT = 800 threads.
// ---------------------------------------------------------------------------
__global__ void prep_kernel(const float* __restrict__ out, const float* __restrict__ tgt)
{
    int tid = threadIdx.x;            // 0..799
    int b = tid / TT;
    int t = tid - b * TT;

    if (tid == 0) g_acc = 0.0;

    __shared__ float sx[NB * TT];
    __shared__ int   sidx[NB * TT];
    __shared__ int   snv[NB];

    const float* tp = tgt + tid * 6;
    float tcls = tp[0];
    float gx = tp[1] * NW;
    float gy = tp[2] * NH;
    float gw = tp[3] * NW;
    float gh = tp[4] * NH;
    float lr = tp[5];
    sx[tid] = tp[1];
    __syncthreads();

    if (t == 0) {
        int nv = 0;
        while (nv < TT && sx[b * TT + nv] != 0.f) nv++;
        snv[b] = nv;
        g_nv[b] = nv;
    }

    // gt box extents for the dense kernel (and for conf_mask0 recompute below)
    g_tA[tid] = make_float4(gx - 0.5f * gw, gx + 0.5f * gw, gy - 0.5f * gh, gy + 0.5f * gh);
    g_tB[tid] = make_float4(gw, gh, 0.6f * (gw * gh), 0.f);

    // best anchor (first-index-wins on ties, matching jnp.argmax)
    int bn = 0;
    float best = -1.f;
    float garea = gw * gh;
#pragma unroll
    for (int k = 0; k < NA; k++) {
        float inter = fminf(gw, c_aw[k]) * fminf(gh, c_ah[k]);
        float iou = inter / (garea + c_aw[k] * c_ah[k] - inter);
        if (iou > best) { best = iou; bn = k; }
    }
    int gi = (int)gx;
    int gj = (int)gy;
    int idx = bn * NHW + gj * NW + gi;

    __syncthreads();   // snv + g_tA/g_tB visible

    bool valid = t < snv[b];
    sidx[tid] = valid ? idx : (-1 - tid);   // unique sentinel for invalid
    __syncthreads();

    if (!valid) return;

    // last-valid-write-wins: target t is the owner iff no later valid target
    // of this batch scatters to the same cell.
    int nv = snv[b];
    for (int t2 = t + 1; t2 < nv; t2++)
        if (sidx[b * TT + t2] == idx) return;

    // -------- sparse contributions for this owned cell --------
    float tx = gx - (float)gi;
    float ty = gy - (float)gj;
    float tw = logf(gw / c_aw[bn]);
    float th = logf(gh / c_ah[bn]);

    const float* op = out + ((b * NA + bn) * 8) * NHW + gj * NW + gi;
    float o0 = op[0];
    float o1 = op[NHW];
    float o2 = op[2 * NHW];
    float o3 = op[3 * NHW];
    float o4 = op[4 * NHW];
    float o5 = op[5 * NHW];
    float o6 = op[6 * NHW];
    float o7 = op[7 * NHW];

    float x = sigmoidf_(o0);
    float y = sigmoidf_(o1);
    float px = x + (float)gi;
    float py = y + (float)gj;
    float pw = expf(o2) * c_aw[bn];
    float ph = expf(o3) * c_ah[bn];

    // tconf = IoU(gt, pred_at)
    float uw = fmaxf(gx + 0.5f * gw, px + 0.5f * pw) - fminf(gx - 0.5f * gw, px - 0.5f * pw);
    float cw = gw + pw - uw;
    float uh = fmaxf(gy + 0.5f * gh, py + 0.5f * ph) - fminf(gy - 0.5f * gh, py - 0.5f * ph);
    float ch = gh + ph - uh;
    float ca = (cw <= 0.f || ch <= 0.f) ? 0.f : cw * ch;
    float tconf = ca / (gw * gh + pw * ph - ca);

    float conf = sigmoidf_(o4);

    // conf_mask0 at this cell (to cancel the dense kernel's default term)
    float xlo = px - 0.5f * pw, xhi = px + 0.5f * pw;
    float ylo = py - 0.5f * ph, yhi = py + 0.5f * ph;
    bool over = iou_over(&g_tA[b * TT], &g_tB[b * TT], nv,
                         xlo, xhi, ylo, yhi, pw, ph, 0.6f * (pw * ph));

    double c = 0.0;
    float dx = x - tx;   c += 0.5 * (double)(dx * dx);
    float dy = y - ty;   c += 0.5 * (double)(dy * dy);
    float dw = o2 - tw;  c += 0.5 * (double)(dw * dw);
    float dh = o3 - th;  c += 0.5 * (double)(dh * dh);
    float dc = conf - tconf;
    c += 2.5 * (double)(dc * dc);                 // 0.5 * OBJECT_SCALE
    if (!over) c -= (double)(0.5f * conf * conf); // cancel dense default term

    // class cross-entropy (log-softmax over 2 logits)
    float m = fmaxf(o5, o6);
    float lse = m + logf(expf(o5 - m) + expf(o6 - m));
    int cls = (int)tcls;
    c += (double)(lse - (cls == 0 ? o5 : o6));

    // lr-conf: loss += 0.5 * mse_half = 0.25*(clr-lr)^2
    float clr = sigmoidf_(o7);
    float dl = clr - lr;
    c += 0.25 * (double)(dl * dl);

    atomicAdd(&g_acc, c);
}

// ---------------------------------------------------------------------------
// Kernel 1: dense no-object confidence term over all nB*nA*nH*nW cells.
// grid = (180, 16), block = 256. blockIdx.y = batch.
// ---------------------------------------------------------------------------
__global__ void conf_kernel(const float* __restrict__ out)
{
    __shared__ float4 sA[TT];
    __shared__ float4 sB[TT];
    __shared__ int   s_nv;
    __shared__ float wsum[8];

    int b = blockIdx.y;
    int tid = threadIdx.x;
    if (tid < TT) {
        sA[tid] = g_tA[b * TT + tid];
        sB[tid] = g_tB[b * TT + tid];
    }
    if (tid == 0) s_nv = g_nv[b];
    __syncthreads();

    int cell = blockIdx.x * 256 + tid;    // 0..46079 within the batch
    int a = cell / NHW;                   // anchor (uniform within a block)
    int hw = cell - a * NHW;
    int j = hw / NW;
    int i = hw - j * NW;

    const float* op = out + ((b * NA + a) * 8) * NHW + hw;
    float o0 = op[0];
    float o1 = op[NHW];
    float o2 = op[2 * NHW];
    float o3 = op[3 * NHW];
    float o4 = op[4 * NHW];

    float px = sigmoidf_(o0) + (float)i;
    float py = sigmoidf_(o1) + (float)j;
    float pw = expf(o2) * c_aw[a];
    float ph = expf(o3) * c_ah[a];

    float xlo = px - 0.5f * pw, xhi = px + 0.5f * pw;
    float ylo = py - 0.5f * ph, yhi = py + 0.5f * ph;
    bool over = iou_over(sA, sB, s_nv, xlo, xhi, ylo, yhi, pw, ph, 0.6f * (pw * ph));

    float conf = sigmoidf_(o4);
    float term = over ? 0.f : 0.5f * conf * conf;

    // block reduction: warp shuffle + smem
#pragma unroll
    for (int off = 16; off > 0; off >>= 1)
        term += __shfl_down_sync(0xffffffffu, term, off);
    if ((tid & 31) == 0) wsum[tid >> 5] = term;
    __syncthreads();
    if (tid == 0) {
        float s = 0.f;
#pragma unroll
        for (int k = 0; k < 8; k++) s += wsum[k];
        atomicAdd(&g_acc, (double)s);
    }
}

__global__ void finalize_kernel(float* __restrict__ o)
{
    o[0] = (float)(g_acc / (double)NB);
}

extern "C" void kernel_launch(void* const* d_in, const int* in_sizes, int n_in,
                              void* d_out, int out_size)
{
    const float* output = (const float*)d_in[0];
    const float* target = (const float*)d_in[1];
    float* out = (float*)d_out;

    prep_kernel<<<1, NB * TT>>>(output, target);
    conf_kernel<<<dim3((NA * NHW) / 256, NB), 256>>>(output);
    finalize_kernel<<<1, 1>>>(out);
}

// round 2
// speedup vs baseline: 1.3309x; 1.3309x over previous
#include <cuda_runtime.h>
#include <math.h>

#define NB 16
#define NA 5
#define NH 96
#define NW 96
#define NHW 9216
#define TT 50
#define DENSE_BLOCKS 180   // 5*9216/256

__constant__ float c_aw[NA] = {1.3221f, 3.19275f, 5.05587f, 9.47112f, 11.2364f};
__constant__ float c_ah[NA] = {1.73145f, 4.00944f, 8.09892f, 4.84053f, 10.0071f};

__device__ double g_acc;
__device__ float4 g_tA[NB * TT];   // sorted-by-area gt extents: xlo, xhi, ylo, yhi
__device__ float  g_bz[NB * TT];   // sorted: 0.6 * gt_area
__device__ int    g_nv[NB];
__device__ float4 g_m0[NB * TT];   // original order: gx, gy, gw, gh
__device__ float  g_lr[NB * TT];
__device__ int4   g_meta[NB * TT]; // idx(within batch), bn, owner, cls

__device__ __forceinline__ float sigmoidf_(float x) { return 1.f / (1.f + __expf(-x)); }

// ---------------------------------------------------------------------------
// Kernel 0: target parsing, anchor argmax, last-write-wins ownership,
// and area-descending sort of the gt boxes (predicate is order-invariant).
// One block of 800 threads; no reads of `output` -> short critical path.
// ---------------------------------------------------------------------------
__global__ void box_prep(const float* __restrict__ tgt)
{
    int tid = threadIdx.x;            // 0..799
    int b = tid / TT;
    int t = tid - b * TT;

    if (tid == 0) g_acc = 0.0;

    __shared__ float sx[NB * TT];
    __shared__ float sarea[NB * TT];
    __shared__ int   sidx[NB * TT];
    __shared__ int   snv[NB];

    const float* tp = tgt + tid * 6;
    float tcls = tp[0];
    float gx = tp[1] * NW;
    float gy = tp[2] * NH;
    float gw = tp[3] * NW;
    float gh = tp[4] * NH;
    float lr = tp[5];
    sx[tid] = tp[1];
    __syncthreads();

    if (t == 0) {
        int nv = 0;
        while (nv < TT && sx[b * TT + nv] != 0.f) nv++;
        snv[b] = nv;
        g_nv[b] = nv;
    }
    __syncthreads();
    int nv = snv[b];
    bool valid = t < nv;

    float area = gw * gh;

    // best anchor (first-index-wins, matching jnp.argmax)
    int bn = 0;
    float best = -1.f;
#pragma unroll
    for (int k = 0; k < NA; k++) {
        float inter = fminf(gw, c_aw[k]) * fminf(gh, c_ah[k]);
        float iou = inter / (area + c_aw[k] * c_ah[k] - inter);
        if (iou > best) { best = iou; bn = k; }
    }
    int gi = (int)gx;
    int gj = (int)gy;
    int idx = bn * NHW + gj * NW + gi;

    sarea[tid] = valid ? area : -1.f;
    sidx[tid] = valid ? idx : (-1 - tid);
    __syncthreads();

    if (!valid) return;

    // rank among valid targets of this batch, by area descending (ties: index)
    int rank = 0;
    for (int k = 0; k < nv; k++) {
        float ak = sarea[b * TT + k];
        if (ak > area || (ak == area && k < t)) rank++;
    }
    // last-valid-write-wins ownership
    bool owner = true;
    for (int t2 = t + 1; t2 < nv; t2++)
        if (sidx[b * TT + t2] == idx) { owner = false; break; }

    g_tA[b * TT + rank] = make_float4(gx - 0.5f * gw, gx + 0.5f * gw,
                                      gy - 0.5f * gh, gy + 0.5f * gh);
    g_bz[b * TT + rank] = 0.6f * area;
    g_m0[b * TT + t] = make_float4(gx, gy, gw, gh);
    g_lr[b * TT + t] = lr;
    g_meta[b * TT + t] = make_int4(idx, bn, owner ? 1 : 0, (int)tcls);
}

// ---------------------------------------------------------------------------
// Kernel 1: fused dense no-object term + sparse per-target loss.
// grid = (181, 16), block = 256. blockIdx.x < 180 -> dense, == 180 -> sparse.
// ---------------------------------------------------------------------------
__global__ void conf_kernel(const float* __restrict__ out)
{
    __shared__ float4 sA[TT];
    __shared__ float  sbz[TT];
    __shared__ int    s_nv;
    __shared__ float  wsum[8];

    int b = blockIdx.y;
    int tid = threadIdx.x;
    if (tid < TT) {
        sA[tid] = g_tA[b * TT + tid];
        sbz[tid] = g_bz[b * TT + tid];
    }
    if (tid == 0) s_nv = g_nv[b];
    __syncthreads();
    int nv = s_nv;

    if (blockIdx.x == DENSE_BLOCKS) {
        // ---------------- sparse path: one thread per target ----------------
        int t = tid;
        if (t >= nv) return;
        int4 meta = g_meta[b * TT + t];
        if (!meta.z) return;                  // not the last writer for its cell

        int idx = meta.x, bn = meta.y, cls = meta.w;
        int hw = idx - bn * NHW;
        int gj = hw / NW;
        int gi = hw - gj * NW;
        float4 m0 = g_m0[b * TT + t];
        float gx = m0.x, gy = m0.y, gw = m0.z, gh = m0.w;
        float lr = g_lr[b * TT + t];

        const float* op = out + ((b * NA + bn) * 8) * NHW + hw;
        float o0 = op[0];
        float o1 = op[NHW];
        float o2 = op[2 * NHW];
        float o3 = op[3 * NHW];
        float o4 = op[4 * NHW];
        float o5 = op[5 * NHW];
        float o6 = op[6 * NHW];
        float o7 = op[7 * NHW];

        float x = sigmoidf_(o0);
        float y = sigmoidf_(o1);
        float px = x + (float)gi;
        float py = y + (float)gj;
        float pw = __expf(o2) * c_aw[bn];
        float ph = __expf(o3) * c_ah[bn];

        float tx = gx - (float)gi;
        float ty = gy - (float)gj;
        float tw = __logf(gw / c_aw[bn]);
        float th = __logf(gh / c_ah[bn]);

        float xlo = px - 0.5f * pw, xhi = px + 0.5f * pw;
        float ylo = py - 0.5f * ph, yhi = py + 0.5f * ph;

        // tconf = IoU(gt, pred_at)
        float iw = fminf(gx + 0.5f * gw, xhi) - fmaxf(gx - 0.5f * gw, xlo);
        float ih = fminf(gy + 0.5f * gh, yhi) - fmaxf(gy - 0.5f * gh, ylo);
        float ca = (iw > 0.f && ih > 0.f) ? iw * ih : 0.f;
        float tconf = ca / (gw * gh + pw * ph - ca);

        float conf = sigmoidf_(o4);

        // conf_mask0 predicate at this cell (identical expression to dense path)
        float c1 = 0.6f * (pw * ph);
        bool over = false;
        for (int k = 0; k < nv; k++) {
            float4 a4 = sA[k];
            float iw2 = fminf(xhi, a4.y) - fmaxf(xlo, a4.x);
            float ih2 = fminf(yhi, a4.w) - fmaxf(ylo, a4.z);
            if (fminf(iw2, ih2) > 0.f && fmaf(1.6f, iw2 * ih2, -sbz[k]) > c1) {
                over = true; break;
            }
        }

        double c = 0.0;
        float dx = x - tx;   c += 0.5 * (double)(dx * dx);
        float dy = y - ty;   c += 0.5 * (double)(dy * dy);
        float dw = o2 - tw;  c += 0.5 * (double)(dw * dw);
        float dh = o3 - th;  c += 0.5 * (double)(dh * dh);
        float dc = conf - tconf;
        c += 2.5 * (double)(dc * dc);                 // 0.5 * OBJECT_SCALE
        if (!over) c -= (double)(0.5f * conf * conf); // cancel dense default term

        float m = fmaxf(o5, o6);
        float lse = m + __logf(__expf(o5 - m) + __expf(o6 - m));
        c += (double)(lse - (cls == 0 ? o5 : o6));

        float clr = sigmoidf_(o7);
        float dl = clr - lr;
        c += 0.25 * (double)(dl * dl);

        atomicAdd(&g_acc, c);
        return;
    }

    // ---------------- dense path: one thread per cell ----------------
    int cell = blockIdx.x * 256 + tid;    // 0..46079 within the batch
    int a = cell / NHW;
    int hw = cell - a * NHW;
    int j = hw / NW;
    int i = hw - j * NW;

    const float* op = out + ((b * NA + a) * 8) * NHW + hw;
    float o0 = op[0];
    float o1 = op[NHW];
    float o2 = op[2 * NHW];
    float o3 = op[3 * NHW];
    float o4 = op[4 * NHW];

    float px = sigmoidf_(o0) + (float)i;
    float py = sigmoidf_(o1) + (float)j;
    float pw = __expf(o2) * c_aw[a];
    float ph = __expf(o3) * c_ah[a];

    float xlo = px - 0.5f * pw, xhi = px + 0.5f * pw;
    float ylo = py - 0.5f * ph, yhi = py + 0.5f * ph;
    float c1 = 0.6f * (pw * ph);

    bool over = false;
    for (int k = 0; k < nv; k++) {
        float4 a4 = sA[k];
        float iw = fminf(xhi, a4.y) - fmaxf(xlo, a4.x);
        float ih = fminf(yhi, a4.w) - fmaxf(ylo, a4.z);
        if (fminf(iw, ih) > 0.f && fmaf(1.6f, iw * ih, -sbz[k]) > c1) {
            over = true; break;
        }
    }

    float conf = sigmoidf_(o4);
    float term = over ? 0.f : 0.5f * conf * conf;

#pragma unroll
    for (int off = 16; off > 0; off >>= 1)
        term += __shfl_down_sync(0xffffffffu, term, off);
    if ((tid & 31) == 0) wsum[tid >> 5] = term;
    __syncthreads();
    if (tid == 0) {
        float s = 0.f;
#pragma unroll
        for (int k = 0; k < 8; k++) s += wsum[k];
        atomicAdd(&g_acc, (double)s);
    }
}

__global__ void finalize_kernel(float* __restrict__ o)
{
    o[0] = (float)(g_acc / (double)NB);
}

extern "C" void kernel_launch(void* const* d_in, const int* in_sizes, int n_in,
                              void* d_out, int out_size)
{
    const float* output = (const float*)d_in[0];
    const float* target = (const float*)d_in[1];
    float* out = (float*)d_out;

    box_prep<<<1, NB * TT>>>(target);
    conf_kernel<<<dim3(DENSE_BLOCKS + 1, NB), 256>>>(output);
    finalize_kernel<<<1, 1>>>(out);
}